// round 9
// baseline (speedup 1.0000x reference)
#include <cuda_runtime.h>
#include <cuda_fp16.h>
#include <cstdint>

#define NN 50000
#define NE 1600000
#define FIN 128
#define FOUT 64
#define NCOLS 640
#define SIDE 320   // src-side row: 4*64 (v logits) + 64 (m_nb)

// ---- scratch ----
__device__ __half g_uH[(size_t)NN * 256];         // u0..u3 (fp16)
__device__ float  g_mself[(size_t)NN * 64];       // m_self (fp32)
__device__ __half g_srcSideH[(size_t)NN * SIDE];  // v0..v3 | m_nb (fp16)
__device__ float  g_Wc[FIN * NCOLS];              // tf32-rounded
__device__ float  g_biasC[NCOLS];
__device__ int    g_cnt[NN];
__device__ int    g_off[NN + 1];
__device__ int    g_cursor[NN];
__device__ int    g_srcSorted[NE];
__device__ int    g_blkSum[64];
__device__ int    g_blkOff[64];

__device__ __forceinline__ unsigned f2tf32(float f) {
    unsigned u;
    asm("cvt.rna.tf32.f32 %0, %1;" : "=r"(u) : "f"(f));
    return u;
}

// ============================================================
// 1) Fold weights: Wc[128][640] (tf32) + biasC[640].
//    Blocks 0..7: (uv,i) products Wt_i @ Wa_i-half via smem staging.
//    Block 8: Wn copy; block 9: Wv copy.
// ============================================================
__global__ __launch_bounds__(256) void prep2_kernel(
        const float* __restrict__ Wt, const float* __restrict__ bt,
        const float* __restrict__ Wa, const float* __restrict__ ba,
        const float* __restrict__ Wn, const float* __restrict__ bn,
        const float* __restrict__ Wv, const float* __restrict__ bv) {
    const int b = blockIdx.x, t = threadIdx.x;
    if (b < 8) {
        const int i = b & 3, uv = b >> 2;
        __shared__ float WtS[128 * 64];   // 32 KB
        __shared__ float WaS[64 * 64];    // 16 KB
        const float* wtg = Wt + (size_t)i * 128 * 64;
        const float* wag = Wa + ((size_t)i * 128 + uv * 64) * 64;
        for (int idx = t; idx < 8192; idx += 256) WtS[idx] = wtg[idx];
        for (int idx = t; idx < 4096; idx += 256) WaS[idx] = wag[idx];
        __syncthreads();
        const int colbase = uv * 256 + i * 64;
        const int cc = t & 31;
        const int rg = t >> 5;
        for (int ro = 0; ro < 16; ro++) {
            const int r = rg * 16 + ro;
            float s0 = 0.f, s1 = 0.f;
            #pragma unroll 8
            for (int k = 0; k < 64; k++) {
                float w = WtS[r * 64 + k];
                s0 = fmaf(w, WaS[k * 64 + cc], s0);
                s1 = fmaf(w, WaS[k * 64 + cc + 32], s1);
            }
            g_Wc[(size_t)r * NCOLS + colbase + cc]      = __uint_as_float(f2tf32(s0));
            g_Wc[(size_t)r * NCOLS + colbase + cc + 32] = __uint_as_float(f2tf32(s1));
        }
        if (t < 64) {
            float sb = 0.f;
            for (int k = 0; k < 64; k++) sb = fmaf(bt[i * 64 + k], WaS[k * 64 + t], sb);
            if (uv == 0) sb += ba[i * 64 + t];
            g_biasC[colbase + t] = sb;
        }
    } else {
        const float* W  = (b == 8) ? Wn : Wv;
        const float* bb = (b == 8) ? bn : bv;
        const int colbase = (b == 8) ? 512 : 576;
        for (int idx = t; idx < 8192; idx += 256) {
            int r = idx >> 6, cc = idx & 63;
            g_Wc[(size_t)r * NCOLS + colbase + cc] = __uint_as_float(f2tf32(W[idx]));
        }
        if (t < 64) g_biasC[colbase + t] = bb[t];
    }
}

// ============================================================
// 2) tf32 tensor-core GEMM: [N x 128] @ [128 x 640]
//    BM=128 BN=128 BK=16, 8 warps (4m x 2n), warp tile 32x64, cp.async 2-stage
// ============================================================
__device__ __forceinline__ void cpa16(void* sdst, const void* gsrc, int nbytes) {
    unsigned sa = (unsigned)__cvta_generic_to_shared(sdst);
    asm volatile("cp.async.ca.shared.global [%0], [%1], 16, %2;\n"
                 :: "r"(sa), "l"(gsrc), "r"(nbytes) : "memory");
}

__global__ __launch_bounds__(256) void gemm_tc(const float* __restrict__ X) {
    __shared__ float As[2][128][20];
    __shared__ float Bs[2][16][136];

    const int tid = threadIdx.x;
    const int wid = tid >> 5, lane = tid & 31;
    const int g = lane >> 2, tc = lane & 3;
    const int wm = wid & 3, wn = wid >> 2;
    const int bm = blockIdx.x * 128;
    const int bn = blockIdx.y * 128;

    const int arow = tid >> 1, ac0 = (tid & 1) * 8;
    const int aok = (bm + arow) < NN ? 16 : 0;
    const float* gx = X + (size_t)(bm + arow) * FIN;
    const int brow = tid >> 4, bc = (tid & 15) * 8;

    float acc[2][8][4];
    #pragma unroll
    for (int mi = 0; mi < 2; mi++)
        #pragma unroll
        for (int ni = 0; ni < 8; ni++)
            #pragma unroll
            for (int q = 0; q < 4; q++) acc[mi][ni][q] = 0.f;

    {
        cpa16(&As[0][arow][ac0], gx + ac0, aok);
        cpa16(&As[0][arow][ac0 + 4], gx + ac0 + 4, aok);
        cpa16(&Bs[0][brow][bc], g_Wc + (size_t)brow * NCOLS + bn + bc, 16);
        cpa16(&Bs[0][brow][bc + 4], g_Wc + (size_t)brow * NCOLS + bn + bc + 4, 16);
        asm volatile("cp.async.commit_group;\n" ::: "memory");
    }

    #pragma unroll
    for (int t = 0; t < 8; t++) {
        const int cur = t & 1;
        if (t < 7) {
            const int nxt = cur ^ 1;
            const int k0g = (t + 1) * 16;
            cpa16(&As[nxt][arow][ac0], gx + k0g + ac0, aok);
            cpa16(&As[nxt][arow][ac0 + 4], gx + k0g + ac0 + 4, aok);
            cpa16(&Bs[nxt][brow][bc], g_Wc + (size_t)(k0g + brow) * NCOLS + bn + bc, 16);
            cpa16(&Bs[nxt][brow][bc + 4], g_Wc + (size_t)(k0g + brow) * NCOLS + bn + bc + 4, 16);
            asm volatile("cp.async.commit_group;\n" ::: "memory");
            asm volatile("cp.async.wait_group 1;\n" ::: "memory");
        } else {
            asm volatile("cp.async.wait_group 0;\n" ::: "memory");
        }
        __syncthreads();

        #pragma unroll
        for (int ks = 0; ks < 2; ks++) {
            const int k0 = ks * 8;
            unsigned Af[2][4];
            #pragma unroll
            for (int mi = 0; mi < 2; mi++) {
                const int m0 = wm * 32 + mi * 16;
                Af[mi][0] = f2tf32(As[cur][m0 + g][k0 + tc]);
                Af[mi][1] = f2tf32(As[cur][m0 + g + 8][k0 + tc]);
                Af[mi][2] = f2tf32(As[cur][m0 + g][k0 + tc + 4]);
                Af[mi][3] = f2tf32(As[cur][m0 + g + 8][k0 + tc + 4]);
            }
            #pragma unroll
            for (int ni = 0; ni < 8; ni++) {
                const int n0 = wn * 64 + ni * 8;
                unsigned B0 = __float_as_uint(Bs[cur][k0 + tc][n0 + g]);
                unsigned B1 = __float_as_uint(Bs[cur][k0 + tc + 4][n0 + g]);
                #pragma unroll
                for (int mi = 0; mi < 2; mi++) {
                    asm volatile(
                        "mma.sync.aligned.m16n8k8.row.col.f32.tf32.tf32.f32 "
                        "{%0,%1,%2,%3}, {%4,%5,%6,%7}, {%8,%9}, {%0,%1,%2,%3};"
                        : "+f"(acc[mi][ni][0]), "+f"(acc[mi][ni][1]),
                          "+f"(acc[mi][ni][2]), "+f"(acc[mi][ni][3])
                        : "r"(Af[mi][0]), "r"(Af[mi][1]), "r"(Af[mi][2]), "r"(Af[mi][3]),
                          "r"(B0), "r"(B1));
                }
            }
        }
        __syncthreads();
    }

    // routing: this warp's 64-col group (0..9)
    const int g64 = (bn >> 6) + wn;

    #pragma unroll
    for (int mi = 0; mi < 2; mi++) {
        #pragma unroll
        for (int ni = 0; ni < 8; ni++) {
            const int loc = ni * 8 + 2 * tc;
            const float bx = g_biasC[g64 * 64 + loc];
            const float by = g_biasC[g64 * 64 + loc + 1];
            const int r0 = bm + wm * 32 + mi * 16 + g;
            const int r1 = r0 + 8;
            float2 o0 = make_float2(acc[mi][ni][0] + bx, acc[mi][ni][1] + by);
            float2 o1 = make_float2(acc[mi][ni][2] + bx, acc[mi][ni][3] + by);
            if (g64 < 4) {                 // u_i -> fp16
                const int cb = g64 * 64 + loc;
                if (r0 < NN) *(__half2*)(g_uH + (size_t)r0 * 256 + cb) = __float22half2_rn(o0);
                if (r1 < NN) *(__half2*)(g_uH + (size_t)r1 * 256 + cb) = __float22half2_rn(o1);
            } else if (g64 < 9) {          // v_i / m_nb -> fp16
                const int cb = (g64 - 4) * 64 + loc;
                if (r0 < NN) *(__half2*)(g_srcSideH + (size_t)r0 * SIDE + cb) = __float22half2_rn(o0);
                if (r1 < NN) *(__half2*)(g_srcSideH + (size_t)r1 * SIDE + cb) = __float22half2_rn(o1);
            } else {                       // m_self -> fp32
                if (r0 < NN) *(float2*)(g_mself + (size_t)r0 * 64 + loc) = o0;
                if (r1 < NN) *(float2*)(g_mself + (size_t)r1 * 64 + loc) = o1;
            }
        }
    }
}

// ============================================================
// 3) CSR-by-dst build (runs on side stream, overlapped with GEMM)
// ============================================================
__global__ void zero_kernel() {
    int i = blockIdx.x * blockDim.x + threadIdx.x;
    if (i < NN) g_cnt[i] = 0;
}

__global__ void hist_kernel(const int* __restrict__ dst) {
    int i = blockIdx.x * blockDim.x + threadIdx.x;
    if (i < NE / 4) {
        int4 d = ((const int4*)dst)[i];
        atomicAdd(&g_cnt[d.x], 1);
        atomicAdd(&g_cnt[d.y], 1);
        atomicAdd(&g_cnt[d.z], 1);
        atomicAdd(&g_cnt[d.w], 1);
    }
}

__global__ void scan1_kernel() {
    __shared__ int sm[1024];
    const int t = threadIdx.x;
    const int i = blockIdx.x * 1024 + t;
    int v = (i < NN) ? g_cnt[i] : 0;
    sm[t] = v;
    __syncthreads();
    #pragma unroll
    for (int ofs = 1; ofs < 1024; ofs <<= 1) {
        int add = (t >= ofs) ? sm[t - ofs] : 0;
        __syncthreads();
        sm[t] += add;
        __syncthreads();
    }
    if (i < NN) g_off[i] = sm[t] - v;
    if (t == 1023) g_blkSum[blockIdx.x] = sm[t];
}

__global__ void scan2_kernel(int nblk) {
    __shared__ int sm[64];
    const int t = threadIdx.x;
    int v = (t < nblk) ? g_blkSum[t] : 0;
    sm[t] = v;
    __syncthreads();
    #pragma unroll
    for (int ofs = 1; ofs < 64; ofs <<= 1) {
        int add = (t >= ofs) ? sm[t - ofs] : 0;
        __syncthreads();
        sm[t] += add;
        __syncthreads();
    }
    if (t < nblk) g_blkOff[t] = sm[t] - v;
    if (t == nblk - 1) g_off[NN] = sm[t];
}

__global__ void scan3_kernel() {
    const int i = blockIdx.x * 1024 + threadIdx.x;
    if (i < NN) {
        int o = g_off[i] + g_blkOff[blockIdx.x];
        g_off[i] = o;
        g_cursor[i] = o;
    }
}

__global__ void scatter_kernel(const int* __restrict__ src, const int* __restrict__ dst) {
    int i = blockIdx.x * blockDim.x + threadIdx.x;
    if (i < NE / 4) {
        int4 s = ((const int4*)src)[i];
        int4 d = ((const int4*)dst)[i];
        g_srcSorted[atomicAdd(&g_cursor[d.x], 1)] = s.x;
        g_srcSorted[atomicAdd(&g_cursor[d.y], 1)] = s.y;
        g_srcSorted[atomicAdd(&g_cursor[d.z], 1)] = s.z;
        g_srcSorted[atomicAdd(&g_cursor[d.w], 1)] = s.w;
    }
}

// ============================================================
// 4) Edge aggregation: one WARP per dst node, half2 per thread,
//    src indices via shfl; self term fused; no atomics, no smem.
// ============================================================
__global__ __launch_bounds__(256) void edge_kernel(float* __restrict__ out) {
    const int warp = threadIdx.x >> 5, lane = threadIdx.x & 31;
    const int n = blockIdx.x * 8 + warp;
    if (n >= NN) return;

    const __half2* up = (const __half2*)g_uH + (size_t)n * 128;
    __half2 uh[4];
    #pragma unroll
    for (int i = 0; i < 4; i++) uh[i] = up[i * 32 + lane];
    const float2 msf = ((const float2*)g_mself)[(size_t)n * 32 + lane];
    const __half2 zero2 = __float2half2_rn(0.f);

    float2 den, num;
    {
        const __half2* vs = (const __half2*)(g_srcSideH + (size_t)n * SIDE);
        __half2 s2 = __hmax2(__hadd2(uh[0], vs[lane]), zero2);
        s2 = __hadd2(s2, __hmax2(__hadd2(uh[1], vs[32 + lane]), zero2));
        s2 = __hadd2(s2, __hmax2(__hadd2(uh[2], vs[64 + lane]), zero2));
        s2 = __hadd2(s2, __hmax2(__hadd2(uh[3], vs[96 + lane]), zero2));
        float2 s = __half22float2(s2);
        float e0 = __expf(0.25f * s.x), e1 = __expf(0.25f * s.y);
        den = make_float2(e0, e1);
        num = make_float2(e0 * msf.x, e1 * msf.y);
    }

    const int b0 = g_off[n], b1 = g_off[n + 1];
    for (int base = b0; base < b1; base += 32) {
        int myIdx = (base + lane < b1) ? g_srcSorted[base + lane] : 0;
        const int cnt = min(32, b1 - base);
        #pragma unroll 4
        for (int j = 0; j < cnt; j++) {
            const int sidx = __shfl_sync(0xffffffff, myIdx, j);
            const __half2* p = (const __half2*)(g_srcSideH + (size_t)sidx * SIDE);
            __half2 s2 = __hmax2(__hadd2(uh[0], p[lane]), zero2);
            s2 = __hadd2(s2, __hmax2(__hadd2(uh[1], p[32 + lane]), zero2));
            s2 = __hadd2(s2, __hmax2(__hadd2(uh[2], p[64 + lane]), zero2));
            s2 = __hadd2(s2, __hmax2(__hadd2(uh[3], p[96 + lane]), zero2));
            float2 mm = __half22float2(p[128 + lane]);
            float2 s = __half22float2(s2);
            float w0 = __expf(0.25f * s.x), w1 = __expf(0.25f * s.y);
            den.x += w0;                den.y += w1;
            num.x = fmaf(w0, mm.x, num.x); num.y = fmaf(w1, mm.y, num.y);
        }
    }
    float2 o;
    o.x = fmaxf(__fdividef(num.x, den.x), 0.f);
    o.y = fmaxf(__fdividef(num.y, den.y), 0.f);
    ((float2*)out)[(size_t)n * 32 + lane] = o;
}

// ============================================================
// Side stream + events for graph-fork (created once at load;
// timing-disabled events are graph-capture legal).
// ============================================================
struct Aux {
    cudaStream_t s2 = 0;
    cudaEvent_t e0 = 0, e1 = 0;
    bool ok = false;
    Aux() {
        cudaStream_t s = 0;
        cudaEvent_t a = 0, b = 0;
        if (cudaStreamCreateWithFlags(&s, cudaStreamNonBlocking) == cudaSuccess &&
            cudaEventCreateWithFlags(&a, cudaEventDisableTiming) == cudaSuccess &&
            cudaEventCreateWithFlags(&b, cudaEventDisableTiming) == cudaSuccess) {
            s2 = s; e0 = a; e1 = b; ok = true;
        }
    }
};
static Aux g_aux;

extern "C" void kernel_launch(void* const* d_in, const int* in_sizes, int n_in,
                              void* d_out, int out_size) {
    const float* x   = (const float*)d_in[0];
    const int*   src = (const int*)d_in[1];
    const int*   dst = (const int*)d_in[2];
    const float* Wv = (const float*)d_in[3];
    const float* bv = (const float*)d_in[4];
    const float* Wn = (const float*)d_in[5];
    const float* bn = (const float*)d_in[6];
    const float* Wt = (const float*)d_in[7];
    const float* bt = (const float*)d_in[8];
    const float* Wa = (const float*)d_in[9];
    const float* ba = (const float*)d_in[10];
    float* out = (float*)d_out;

    const int NB = (NN + 1023) / 1024;   // 49
    const bool fork = g_aux.ok;
    cudaStream_t sc = fork ? g_aux.s2 : (cudaStream_t)0;

    if (fork) {
        cudaEventRecord(g_aux.e0, 0);
        cudaStreamWaitEvent(g_aux.s2, g_aux.e0, 0);
    }

    // CSR chain (side stream when available)
    zero_kernel<<<(NN + 255) / 256, 256, 0, sc>>>();
    hist_kernel<<<(NE / 4 + 255) / 256, 256, 0, sc>>>(dst);
    scan1_kernel<<<NB, 1024, 0, sc>>>();
    scan2_kernel<<<1, 64, 0, sc>>>(NB);
    scan3_kernel<<<NB, 1024, 0, sc>>>();
    scatter_kernel<<<(NE / 4 + 255) / 256, 256, 0, sc>>>(src, dst);
    if (fork) cudaEventRecord(g_aux.e1, g_aux.s2);

    // Compute chain (main stream)
    prep2_kernel<<<10, 256>>>(Wt, bt, Wa, ba, Wn, bn, Wv, bv);
    dim3 ggrid((NN + 127) / 128, 5);
    gemm_tc<<<ggrid, 256>>>(x);

    if (fork) cudaStreamWaitEvent(0, g_aux.e1, 0);
    edge_kernel<<<(NN + 7) / 8, 256>>>(out);
}